// round 14
// baseline (speedup 1.0000x reference)
#include <cuda_runtime.h>
#include <cuda_fp16.h>
#include <stdint.h>

#define M_DIM 4096
#define N_DIM 4096
#define K_DIM 1024
#define KC    512     // reference panel size (two sequential chains + RN add)

typedef unsigned long long ull;

__device__ float g_xT[(size_t)K_DIM * M_DIM];  // decoded X, k-major [K][M]
__device__ float g_wT[(size_t)K_DIM * N_DIM];  // decoded W, k-major [K][N]
__device__ float g_p[(size_t)M_DIM * N_DIM];   // phase-1 partials

// ---------------------------------------------------------------------------
// helpers
// ---------------------------------------------------------------------------
__device__ __forceinline__ uint32_t smem_u32(const void* p) {
    uint32_t a;
    asm("{ .reg .u64 t; cvta.to.shared.u64 t, %1; cvt.u32.u64 %0, t; }"
        : "=r"(a) : "l"(p));
    return a;
}
#define CP16(saddr, gptr) \
    asm volatile("cp.async.cg.shared.global [%0], [%1], 16;" \
                 :: "r"(saddr), "l"(gptr) : "memory")
#define CP_COMMIT() asm volatile("cp.async.commit_group;" ::: "memory")
#define CP_WAIT3()  asm volatile("cp.async.wait_group 3;" ::: "memory")

__device__ __forceinline__ ull pack2(float x) {
    ull r;
    asm("mov.b64 %0, {%1, %1};" : "=l"(r) : "f"(x));
    return r;
}
__device__ __forceinline__ void fma2(ull& d, ull a, ull b) {
    asm("fma.rn.f32x2 %0, %1, %2, %0;" : "+l"(d) : "l"(a), "l"(b));
}
__device__ __forceinline__ float lo2(ull v) {
    return __uint_as_float((unsigned int)(v & 0xffffffffull));
}
__device__ __forceinline__ float hi2(ull v) {
    return __uint_as_float((unsigned int)(v >> 32));
}

// ---------------------------------------------------------------------------
// Decode + transpose: pulse[(m*K+k)*16] -> outT[k*4096 + m]  (exact values)
// ---------------------------------------------------------------------------
__global__ void decode_transpose_kernel(const float* __restrict__ pulse,
                                        float* __restrict__ outT) {
    int i = blockIdx.x * blockDim.x + threadIdx.x;   // i = k*4096 + m
    int m = i & 4095;
    int k = i >> 12;
    const float4* p4 =
        reinterpret_cast<const float4*>(pulse + ((size_t)m * K_DIM + k) * 16);
    float4 a = p4[0], b = p4[1], c = p4[2], d = p4[3];
    float p[16] = {a.x, a.y, a.z, a.w, b.x, b.y, b.z, b.w,
                   c.x, c.y, c.z, c.w, d.x, d.y, d.z, d.w};
    unsigned int bits = 0;
#pragma unroll
    for (int j = 0; j < 16; j++)
        bits |= ((unsigned int)(p[j] > 0.5f)) << (15 - j);
    outT[i] = __half2float(__ushort_as_half((unsigned short)bits));
}

// ---------------------------------------------------------------------------
// Half-K GEMM phase: cp.async 5-stage pipeline (4-tile lookahead) +
// fragment double buffering + LDS.128-only fragment loads.
// Per output: strict k-ascending fp32 RN chain over [koff, koff+KC)
// (FFMA2 = per-lane IEEE RN; pairs over adjacent n; chain order unchanged).
// BM=BN=128, TILE_K=16, 256 threads, 8x8 microtile.
// n map: n = n0 + tx*4 + (0..3) + 64*jj, jj=0..1.
// ---------------------------------------------------------------------------
#define TILE_K 16
#define NT (KC / TILE_K)                    // 32
#define STAGE_FLOATS (TILE_K * 128)         // 2048
#define NSTAGE 5
#define SMEM_BYTES (NSTAGE * STAGE_FLOATS * 2 * 4)  // 81920

template <bool PHASE2>
__global__ __launch_bounds__(256, 2)
void gemm_phase_kernel(const float* __restrict__ AT,   // [K][M]
                       const float* __restrict__ BT,   // [K][N]
                       float* __restrict__ part,
                       float* __restrict__ out, int koff) {
    extern __shared__ float sm[];
    float* Asm = sm;                               // [NSTAGE][16][128]
    float* Bsm = sm + NSTAGE * STAGE_FLOATS;

    const int tid = threadIdx.x;
    const int tx = tid & 15;
    const int ty = tid >> 4;
    const int m0 = blockIdx.y * 128;
    const int n0 = blockIdx.x * 128;

    // copy indexing: tile = 16 rows x 32 chunks(16B); 512 chunks; 2/thread/op
    const int r0 = tid >> 5;                // row 0..7
    const int c0 = (tid & 31) * 4;
    const int r1 = r0 + 8;                  // row 8..15

    const uint32_t sA = smem_u32(Asm);
    const uint32_t sB = smem_u32(Bsm);

    ull acc2[8][4];
#pragma unroll
    for (int i = 0; i < 8; i++)
#pragma unroll
        for (int j = 0; j < 4; j++) acc2[i][j] = 0ull;

#define ISSUE(T)                                                              \
    do {                                                                      \
        const int _st = (T) % NSTAGE;                                         \
        const size_t _k0 = (size_t)(koff + (T) * TILE_K);                     \
        CP16(sA + (uint32_t)(_st * STAGE_FLOATS + r0 * 128 + c0) * 4,         \
             AT + (_k0 + r0) * M_DIM + m0 + c0);                              \
        CP16(sA + (uint32_t)(_st * STAGE_FLOATS + r1 * 128 + c0) * 4,         \
             AT + (_k0 + r1) * M_DIM + m0 + c0);                              \
        CP16(sB + (uint32_t)(_st * STAGE_FLOATS + r0 * 128 + c0) * 4,         \
             BT + (_k0 + r0) * N_DIM + n0 + c0);                              \
        CP16(sB + (uint32_t)(_st * STAGE_FLOATS + r1 * 128 + c0) * 4,         \
             BT + (_k0 + r1) * N_DIM + n0 + c0);                              \
        CP_COMMIT();                                                          \
    } while (0)

    ISSUE(0);
    ISSUE(1);
    ISSUE(2);
    ISSUE(3);

    for (int t = 0; t < NT; t++) {
        CP_WAIT3();          // tile t landed (<=3 younger groups in flight)
        __syncthreads();     // all threads' copies of tile t visible;
                             // also orders compute(t-1) before ISSUE(t+4)
                             // (stage (t+4)%5 == (t-1)%5)
        if (t + 4 < NT) ISSUE(t + 4);

        const int st = t % NSTAGE;
        const float* as = Asm + st * STAGE_FLOATS;
        const float* bs = Bsm + st * STAGE_FLOATS;

        // fragment double buffers (all LDS.128)
        float4 afA[2], afB[2];
        ulonglong2 bq0[2], bq1[2];
        afA[0] = *reinterpret_cast<const float4*>(as + ty * 8);
        afB[0] = *reinterpret_cast<const float4*>(as + ty * 8 + 4);
        bq0[0] = *reinterpret_cast<const ulonglong2*>(bs + tx * 4);
        bq1[0] = *reinterpret_cast<const ulonglong2*>(bs + tx * 4 + 64);

#pragma unroll
        for (int k = 0; k < TILE_K; k++) {
            const int cur = k & 1, nxt = cur ^ 1;
            if (k + 1 < TILE_K) {
                const float* as1 = as + (k + 1) * 128;
                const float* bs1 = bs + (k + 1) * 128;
                afA[nxt] = *reinterpret_cast<const float4*>(as1 + ty * 8);
                afB[nxt] = *reinterpret_cast<const float4*>(as1 + ty * 8 + 4);
                bq0[nxt] = *reinterpret_cast<const ulonglong2*>(bs1 + tx * 4);
                bq1[nxt] =
                    *reinterpret_cast<const ulonglong2*>(bs1 + tx * 4 + 64);
            }
            ull ar2[8];
            ar2[0] = pack2(afA[cur].x); ar2[1] = pack2(afA[cur].y);
            ar2[2] = pack2(afA[cur].z); ar2[3] = pack2(afA[cur].w);
            ar2[4] = pack2(afB[cur].x); ar2[5] = pack2(afB[cur].y);
            ar2[6] = pack2(afB[cur].z); ar2[7] = pack2(afB[cur].w);
            const ull br2[4] = {bq0[cur].x, bq0[cur].y,
                                bq1[cur].x, bq1[cur].y};
#pragma unroll
            for (int i = 0; i < 8; i++)
#pragma unroll
                for (int j = 0; j < 4; j++)
                    fma2(acc2[i][j], ar2[i], br2[j]);
        }
    }
#undef ISSUE

    if (!PHASE2) {
#pragma unroll
        for (int i = 0; i < 8; i++) {
            const int m = m0 + ty * 8 + i;
            float* dst = part + (size_t)m * N_DIM + n0 + tx * 4;
            float4 v0 = make_float4(lo2(acc2[i][0]), hi2(acc2[i][0]),
                                    lo2(acc2[i][1]), hi2(acc2[i][1]));
            float4 v1 = make_float4(lo2(acc2[i][2]), hi2(acc2[i][2]),
                                    lo2(acc2[i][3]), hi2(acc2[i][3]));
            *reinterpret_cast<float4*>(dst) = v0;
            *reinterpret_cast<float4*>(dst + 64) = v1;
        }
    } else {
#pragma unroll
        for (int i = 0; i < 8; i++) {
            const int m = m0 + ty * 8 + i;
            const float* psrc = part + (size_t)m * N_DIM + n0 + tx * 4;
#pragma unroll
            for (int jj = 0; jj < 2; jj++) {
                float4 pv = *reinterpret_cast<const float4*>(psrc + 64 * jj);
                float rv[4] = {pv.x + lo2(acc2[i][jj * 2]),
                               pv.y + hi2(acc2[i][jj * 2]),
                               pv.z + lo2(acc2[i][jj * 2 + 1]),
                               pv.w + hi2(acc2[i][jj * 2 + 1])};
#pragma unroll
                for (int e = 0; e < 4; e++) {
                    const int n = n0 + tx * 4 + e + 64 * jj;
                    unsigned int u = (unsigned int)
                        __half_as_ushort(__float2half_rn(rv[e]));
                    float4* dst = reinterpret_cast<float4*>(
                        out + ((size_t)m * N_DIM + n) * 16);
#pragma unroll
                    for (int q = 0; q < 4; q++) {
                        float4 o;
                        o.x = __uint_as_float(
                            (unsigned)(((int)(u << (16 + q * 4 + 0))) >> 31)
                            & 0x3F800000u);
                        o.y = __uint_as_float(
                            (unsigned)(((int)(u << (16 + q * 4 + 1))) >> 31)
                            & 0x3F800000u);
                        o.z = __uint_as_float(
                            (unsigned)(((int)(u << (16 + q * 4 + 2))) >> 31)
                            & 0x3F800000u);
                        o.w = __uint_as_float(
                            (unsigned)(((int)(u << (16 + q * 4 + 3))) >> 31)
                            & 0x3F800000u);
                        dst[q] = o;
                    }
                }
            }
        }
    }
}

// ---------------------------------------------------------------------------
extern "C" void kernel_launch(void* const* d_in, const int* in_sizes, int n_in,
                              void* d_out, int out_size) {
    const float* x_pulse = (const float*)d_in[0];
    const float* w_pulse = (const float*)d_in[1];
    float* out = (float*)d_out;

    float *gx = nullptr, *gw = nullptr, *gp = nullptr;
    cudaGetSymbolAddress((void**)&gx, g_xT);
    cudaGetSymbolAddress((void**)&gw, g_wT);
    cudaGetSymbolAddress((void**)&gp, g_p);

    const int n_el = M_DIM * K_DIM;

    decode_transpose_kernel<<<n_el / 256, 256>>>(x_pulse, gx);
    decode_transpose_kernel<<<n_el / 256, 256>>>(w_pulse, gw);

    cudaFuncSetAttribute(gemm_phase_kernel<false>,
                         cudaFuncAttributeMaxDynamicSharedMemorySize,
                         SMEM_BYTES);
    cudaFuncSetAttribute(gemm_phase_kernel<true>,
                         cudaFuncAttributeMaxDynamicSharedMemorySize,
                         SMEM_BYTES);

    dim3 grid(N_DIM / 128, M_DIM / 128);  // 32 x 32
    gemm_phase_kernel<false><<<grid, 256, SMEM_BYTES>>>(gx, gw, gp, out, 0);
    gemm_phase_kernel<true><<<grid, 256, SMEM_BYTES>>>(gx, gw, gp, out, KC);
}